// round 1
// baseline (speedup 1.0000x reference)
#include <cuda_runtime.h>
#include <math.h>

// ---------------- problem constants ----------------
#define L_LAYERS 2
#define S_LEN    1024
#define HID      2048
#define NH       16
#define HD       128
#define INTER    5632
#define VOCAB    32000
#define EPS_RMS  1e-5f
#define ATT_SCALE 0.08838834764831845f  // 1/sqrt(128)

// ---------------- scratch (device globals; no allocs allowed) ----------------
__device__ float g_ws[(size_t)VOCAB * HID];     // dequantized weight scratch (262MB, reused)
__device__ float g_h[S_LEN * HID];
__device__ float g_x[S_LEN * HID];
__device__ float g_q[S_LEN * HID];
__device__ float g_k[S_LEN * HID];
__device__ float g_v[S_LEN * HID];
__device__ float g_ctx[S_LEN * HID];
__device__ float g_a[S_LEN * HID];
__device__ float g_gate[S_LEN * INTER];
__device__ float g_up[S_LEN * INTER];

// ---------------- dequant: one warp per group of 32 along K ----------------
__global__ void dequant_kernel(const float* __restrict__ w, float* __restrict__ o, int ngroups) {
    int gid  = (blockIdx.x * blockDim.x + threadIdx.x) >> 5;
    int lane = threadIdx.x & 31;
    if (gid >= ngroups) return;
    size_t idx = (size_t)gid * 32 + lane;
    float v = w[idx];
    float a = fabsf(v);
#pragma unroll
    for (int off = 16; off; off >>= 1) a = fmaxf(a, __shfl_xor_sync(0xffffffffu, a, off));
    float s = a / 7.0f + 1e-12f;
    float q = fminf(fmaxf(rintf(v / s), -8.0f), 7.0f);
    o[idx] = q * s;
}

// ---------------- embedding gather ----------------
__global__ void embed_kernel(const int* __restrict__ ids, const float* __restrict__ ew,
                             float* __restrict__ h) {
    int s = blockIdx.x;
    int tok = ids[s];
    const float4* src = (const float4*)(ew + (size_t)tok * HID);
    float4* dst = (float4*)(h + (size_t)s * HID);
    for (int i = threadIdx.x; i < HID / 4; i += blockDim.x) dst[i] = src[i];
}

// ---------------- rmsnorm (one block per row) ----------------
__global__ void rmsnorm_kernel(const float* __restrict__ x, const float* __restrict__ w,
                               float* __restrict__ o) {
    int row = blockIdx.x;
    const float* xr = x + (size_t)row * HID;
    float s = 0.f;
    for (int i = threadIdx.x; i < HID; i += 256) { float v = xr[i]; s += v * v; }
#pragma unroll
    for (int off = 16; off; off >>= 1) s += __shfl_xor_sync(0xffffffffu, s, off);
    __shared__ float red[8];
    __shared__ float rtot;
    if ((threadIdx.x & 31) == 0) red[threadIdx.x >> 5] = s;
    __syncthreads();
    if (threadIdx.x == 0) {
        float t = 0.f;
#pragma unroll
        for (int i = 0; i < 8; ++i) t += red[i];
        rtot = rsqrtf(t / (float)HID + EPS_RMS);
    }
    __syncthreads();
    float r = rtot;
    float* orow = o + (size_t)row * HID;
    for (int i = threadIdx.x; i < HID; i += 256) orow[i] = xr[i] * r * w[i];
}

// ---------------- rope (llama half-split), in-place on q and k ----------------
__global__ void rope_kernel(float* __restrict__ qb, float* __restrict__ kb,
                            const int* __restrict__ pos_ptr) {
    int s = blockIdx.x, h = blockIdx.y, d = threadIdx.x;  // d in [0,64)
    int pos = pos_ptr[0] + s;
    float invf = (float)exp(-((double)(2 * d) / 128.0) * log(10000.0));
    float ang  = (float)pos * invf;
    float cs = (float)cos((double)ang);
    float sn = (float)sin((double)ang);
    size_t base = (size_t)s * HID + h * HD;
    float x1 = qb[base + d], x2 = qb[base + d + 64];
    qb[base + d]      = x1 * cs - x2 * sn;
    qb[base + d + 64] = x2 * cs + x1 * sn;
    x1 = kb[base + d]; x2 = kb[base + d + 64];
    kb[base + d]      = x1 * cs - x2 * sn;
    kb[base + d + 64] = x2 * cs + x1 * sn;
}

// ---------------- SGEMM-NT: C[M,N] = A[M,K] * B[N,K]^T (+ Res) ----------------
// 128x128 tile, BK=16, 256 threads, 8x8 per thread. M,N mult of 128, K mult of 16.
__global__ void __launch_bounds__(256) sgemm_nt(const float* __restrict__ A,
                                                const float* __restrict__ B,
                                                const float* __restrict__ Res,
                                                float* __restrict__ C,
                                                int M, int N, int K) {
    __shared__ float As[16 * 132];
    __shared__ float Bs[16 * 132];
    const int tid = threadIdx.x;
    const int bm = blockIdx.y * 128;
    const int bn = blockIdx.x * 128;
    const int lrow = tid >> 2;
    const int lk = (tid & 3) << 2;
    const int ro = (tid >> 4) << 3;
    const int co = (tid & 15) << 3;
    const float* Ab = A + (size_t)bm * K;
    const float* Bb = B + (size_t)bn * K;
    float acc[8][8];
#pragma unroll
    for (int i = 0; i < 8; ++i)
#pragma unroll
        for (int j = 0; j < 8; ++j) acc[i][j] = 0.f;

    for (int k0 = 0; k0 < K; k0 += 16) {
#pragma unroll
        for (int p = 0; p < 2; ++p) {
            int r = lrow + p * 64;
            float4 ta = *(const float4*)(Ab + (size_t)r * K + k0 + lk);
            float4 tb = *(const float4*)(Bb + (size_t)r * K + k0 + lk);
            As[(lk + 0) * 132 + r] = ta.x; As[(lk + 1) * 132 + r] = ta.y;
            As[(lk + 2) * 132 + r] = ta.z; As[(lk + 3) * 132 + r] = ta.w;
            Bs[(lk + 0) * 132 + r] = tb.x; Bs[(lk + 1) * 132 + r] = tb.y;
            Bs[(lk + 2) * 132 + r] = tb.z; Bs[(lk + 3) * 132 + r] = tb.w;
        }
        __syncthreads();
#pragma unroll
        for (int kk = 0; kk < 16; ++kk) {
            float a[8], b[8];
            *(float4*)(a)     = *(const float4*)(&As[kk * 132 + ro]);
            *(float4*)(a + 4) = *(const float4*)(&As[kk * 132 + ro + 4]);
            *(float4*)(b)     = *(const float4*)(&Bs[kk * 132 + co]);
            *(float4*)(b + 4) = *(const float4*)(&Bs[kk * 132 + co + 4]);
#pragma unroll
            for (int i = 0; i < 8; ++i)
#pragma unroll
                for (int j = 0; j < 8; ++j) acc[i][j] += a[i] * b[j];
        }
        __syncthreads();
    }
#pragma unroll
    for (int i = 0; i < 8; ++i) {
        size_t roff = (size_t)(bm + ro + i) * N + bn + co;
#pragma unroll
        for (int j = 0; j < 8; j += 4) {
            float4 r4;
            r4.x = acc[i][j]; r4.y = acc[i][j + 1]; r4.z = acc[i][j + 2]; r4.w = acc[i][j + 3];
            if (Res) {
                float4 rr = *(const float4*)(Res + roff + j);
                r4.x += rr.x; r4.y += rr.y; r4.z += rr.z; r4.w += rr.w;
            }
            *(float4*)(C + roff + j) = r4;
        }
    }
}

// ---------------- flash attention, fp32, 64q x 32k tiles ----------------
// grid (NH, S/64), block 256. thread = (r,c): r=query row in tile, c=quarter of HD.
__global__ void __launch_bounds__(256) attn_kernel(const float* __restrict__ q,
                                                   const float* __restrict__ k,
                                                   const float* __restrict__ v,
                                                   float* __restrict__ ctx,
                                                   const int* __restrict__ pos_ptr) {
    __shared__ float Ks[32 * 129];
    __shared__ float Vs[32 * 129];
    __shared__ float Ps[64 * 33];
    const int h = blockIdx.x;
    const int qt = blockIdx.y;
    const int tid = threadIdx.x;
    const int r = tid >> 2;
    const int c = tid & 3;
    const int pid = pos_ptr[0];
    const int s = qt * 64 + r;
    const int pos = pid + s;

    float qreg[32], o[32];
    const float* qp = q + (size_t)s * HID + h * HD + c * 32;
#pragma unroll
    for (int i = 0; i < 32; ++i) { qreg[i] = qp[(i + 8 * c) & 31]; o[i] = 0.f; }
    float m = -1e30f, l = 0.f;

    int maxpos = pid + qt * 64 + 63;
    int ntiles = maxpos / 32 + 1;
    if (ntiles > S_LEN / 32) ntiles = S_LEN / 32;

    for (int jt = 0; jt < ntiles; ++jt) {
        __syncthreads();
        for (int idx = tid; idx < 32 * 128; idx += 256) {
            int row = idx >> 7, col = idx & 127;
            size_t g = (size_t)(jt * 32 + row) * HID + h * HD + col;
            Ks[row * 129 + col] = k[g];
            Vs[row * 129 + col] = v[g];
        }
        __syncthreads();

        float tmax = -1e30f;
        for (int j = 0; j < 32; ++j) {
            const float* kr = &Ks[j * 129 + c * 32];
            float p = 0.f;
#pragma unroll
            for (int i = 0; i < 32; ++i) p += qreg[i] * kr[(i + 8 * c) & 31];
            p += __shfl_xor_sync(0xffffffffu, p, 1);
            p += __shfl_xor_sync(0xffffffffu, p, 2);
            float val = ((jt * 32 + j) <= pos) ? p * ATT_SCALE : -1e30f;
            tmax = fmaxf(tmax, val);
            if ((j & 3) == c) Ps[r * 33 + j] = val;
        }
        __syncwarp();
        float mnew = fmaxf(m, tmax);
        float sf = expf(m - mnew);
        float tsum = 0.f;
#pragma unroll
        for (int jj = 0; jj < 8; ++jj) {
            int j = jj * 4 + c;
            float e = expf(Ps[r * 33 + j] - mnew);
            Ps[r * 33 + j] = e;
            tsum += e;
        }
        tsum += __shfl_xor_sync(0xffffffffu, tsum, 1);
        tsum += __shfl_xor_sync(0xffffffffu, tsum, 2);
        __syncwarp();
        l = l * sf + tsum;
        m = mnew;
#pragma unroll
        for (int i = 0; i < 32; ++i) o[i] *= sf;
        for (int j = 0; j < 32; ++j) {
            float pv = Ps[r * 33 + j];
            const float* vr = &Vs[j * 129 + c * 32];
#pragma unroll
            for (int i = 0; i < 32; ++i) o[i] += pv * vr[(i + 8 * c) & 31];
        }
    }
    float inv = 1.f / l;
    float* cp = ctx + (size_t)s * HID + h * HD + c * 32;
#pragma unroll
    for (int i = 0; i < 32; ++i) cp[(i + 8 * c) & 31] = o[i] * inv;
}

// ---------------- SwiGLU elementwise: up *= gate * sigmoid(gate) ----------------
__global__ void silu_mul_kernel(float* __restrict__ up, const float* __restrict__ gate, int n) {
    int i = blockIdx.x * blockDim.x + threadIdx.x;
    if (i < n) {
        float g = gate[i];
        float sg = 1.f / (1.f + expf(-g));
        up[i] = up[i] * g * sg;
    }
}

// ---------------- host orchestration ----------------
static void dequant(const float* w, float* dst, size_t nelem) {
    int ngroups = (int)(nelem / 32);
    int blocks = (int)((nelem + 255) / 256);
    dequant_kernel<<<blocks, 256>>>(w, dst, ngroups);
}

extern "C" void kernel_launch(void* const* d_in, const int* in_sizes, int n_in,
                              void* d_out, int out_size) {
    const int*   input_ids = (const int*)d_in[0];
    // d_in[1] kv_cache (zeros; fully overwritten by masked region) -- unused
    // d_in[2] kv_cache_slots (arange) -- unused
    const int*   pos_id    = (const int*)d_in[3];
    const float* embed_w   = (const float*)d_in[4];
    const float* in_ln_w   = (const float*)d_in[5];
    const float* post_ln_w = (const float*)d_in[6];
    const float* final_ln  = (const float*)d_in[7];
    const float* q_w       = (const float*)d_in[8];
    const float* k_w       = (const float*)d_in[9];
    const float* v_w       = (const float*)d_in[10];
    const float* o_w       = (const float*)d_in[11];
    const float* gate_w    = (const float*)d_in[12];
    const float* up_w      = (const float*)d_in[13];
    const float* down_w    = (const float*)d_in[14];
    const float* lm_head_w = (const float*)d_in[15];
    float* out = (float*)d_out;

    float *p_ws, *p_h, *p_x, *p_q, *p_k, *p_v, *p_ctx, *p_a, *p_gate, *p_up;
    cudaGetSymbolAddress((void**)&p_ws, g_ws);
    cudaGetSymbolAddress((void**)&p_h, g_h);
    cudaGetSymbolAddress((void**)&p_x, g_x);
    cudaGetSymbolAddress((void**)&p_q, g_q);
    cudaGetSymbolAddress((void**)&p_k, g_k);
    cudaGetSymbolAddress((void**)&p_v, g_v);
    cudaGetSymbolAddress((void**)&p_ctx, g_ctx);
    cudaGetSymbolAddress((void**)&p_a, g_a);
    cudaGetSymbolAddress((void**)&p_gate, g_gate);
    cudaGetSymbolAddress((void**)&p_up, g_up);

    embed_kernel<<<S_LEN, 256>>>(input_ids, embed_w, p_h);

    for (int l = 0; l < L_LAYERS; ++l) {
        const size_t wsq = (size_t)HID * HID;
        const size_t wsg = (size_t)INTER * HID;

        rmsnorm_kernel<<<S_LEN, 256>>>(p_h, in_ln_w + l * HID, p_x);

        dequant(q_w + l * wsq, p_ws, wsq);
        sgemm_nt<<<dim3(HID / 128, S_LEN / 128), 256>>>(p_x, p_ws, nullptr, p_q, S_LEN, HID, HID);
        dequant(k_w + l * wsq, p_ws, wsq);
        sgemm_nt<<<dim3(HID / 128, S_LEN / 128), 256>>>(p_x, p_ws, nullptr, p_k, S_LEN, HID, HID);
        dequant(v_w + l * wsq, p_ws, wsq);
        sgemm_nt<<<dim3(HID / 128, S_LEN / 128), 256>>>(p_x, p_ws, nullptr, p_v, S_LEN, HID, HID);

        rope_kernel<<<dim3(S_LEN, NH), 64>>>(p_q, p_k, pos_id);

        attn_kernel<<<dim3(NH, S_LEN / 64), 256>>>(p_q, p_k, p_v, p_ctx, pos_id);

        dequant(o_w + l * wsq, p_ws, wsq);
        sgemm_nt<<<dim3(HID / 128, S_LEN / 128), 256>>>(p_ctx, p_ws, p_h, p_a, S_LEN, HID, HID);

        rmsnorm_kernel<<<S_LEN, 256>>>(p_a, post_ln_w + l * HID, p_x);

        dequant(gate_w + l * wsg, p_ws, wsg);
        sgemm_nt<<<dim3(INTER / 128, S_LEN / 128), 256>>>(p_x, p_ws, nullptr, p_gate, S_LEN, INTER, HID);
        dequant(up_w + l * wsg, p_ws, wsg);
        sgemm_nt<<<dim3(INTER / 128, S_LEN / 128), 256>>>(p_x, p_ws, nullptr, p_up, S_LEN, INTER, HID);

        silu_mul_kernel<<<(S_LEN * INTER + 255) / 256, 256>>>(p_up, p_gate, S_LEN * INTER);

        dequant(down_w + l * wsg, p_ws, wsg);
        sgemm_nt<<<dim3(HID / 128, S_LEN / 128), 256>>>(p_up, p_ws, p_a, p_h, S_LEN, HID, INTER);
    }

    rmsnorm_kernel<<<S_LEN, 256>>>(p_h, final_ln, p_x);
    dequant(lm_head_w, p_ws, (size_t)VOCAB * HID);
    sgemm_nt<<<dim3(VOCAB / 128, S_LEN / 128), 256>>>(p_x, p_ws, nullptr, out, S_LEN, VOCAB, HID);
}

// round 3
// speedup vs baseline: 2.0228x; 2.0228x over previous
#include <cuda_runtime.h>
#include <cuda_bf16.h>
#include <stdint.h>
#include <math.h>

// ---------------- problem constants ----------------
#define L_LAYERS 2
#define S_LEN    1024
#define HID      2048
#define NH       16
#define HD       128
#define INTER    5632
#define VOCAB    32000
#define EPS_RMS  1e-5f
#define ATT_SCALE 0.08838834764831845f  // 1/sqrt(128)
#define QKV_N    (3 * HID)    // 6144
#define GU_N     (2 * INTER)  // 11264

// ---------------- GEMM tile config ----------------
#define BM 128
#define BN 128
#define KC 32                     // K elems per stage
#define NSTAGE 4
#define TILEB 8192                // one 128x32 bf16 tile: 128 rows x 64B
#define STAGE_BYTES (4 * TILEB)   // Ah, Al, Bh, Bl
#define GEMM_SMEM (NSTAGE * STAGE_BYTES)   // 131072

// ---------------- scratch (device globals; no allocs allowed) ----------------
__device__ __align__(1024) __nv_bfloat16 g_wh[(size_t)VOCAB * HID];
__device__ __align__(1024) __nv_bfloat16 g_wl[(size_t)VOCAB * HID];
__device__ __align__(1024) __nv_bfloat16 g_xh[(size_t)S_LEN * INTER];
__device__ __align__(1024) __nv_bfloat16 g_xl[(size_t)S_LEN * INTER];
__device__ __align__(1024) float g_h[S_LEN * HID];
__device__ __align__(1024) float g_a[S_LEN * HID];
__device__ __align__(1024) float g_qkv[(size_t)S_LEN * QKV_N];
__device__ __align__(1024) float g_gu[(size_t)S_LEN * GU_N];

// ---------------- PTX helpers (sm_80-portable only) ----------------
__device__ __forceinline__ uint32_t smem_u32(const void* p) {
    uint32_t r;
    asm("{ .reg .u64 t; cvta.to.shared.u64 t, %1; cvt.u32.u64 %0, t; }" : "=r"(r) : "l"(p));
    return r;
}
__device__ __forceinline__ void cpa16(uint32_t s, const void* g) {
    asm volatile("cp.async.cg.shared.global [%0], [%1], 16;" :: "r"(s), "l"(g));
}
__device__ __forceinline__ void ldsm4(uint32_t* r, uint32_t addr) {
    asm volatile("ldmatrix.sync.aligned.m8n8.x4.shared.b16 {%0,%1,%2,%3}, [%4];"
                 : "=r"(r[0]), "=r"(r[1]), "=r"(r[2]), "=r"(r[3]) : "r"(addr));
}
__device__ __forceinline__ void mma16816(float* d, const uint32_t* a, uint32_t b0, uint32_t b1) {
    asm volatile("mma.sync.aligned.m16n8k16.row.col.f32.bf16.bf16.f32 "
                 "{%0,%1,%2,%3}, {%4,%5,%6,%7}, {%8,%9}, {%0,%1,%2,%3};"
                 : "+f"(d[0]), "+f"(d[1]), "+f"(d[2]), "+f"(d[3])
                 : "r"(a[0]), "r"(a[1]), "r"(a[2]), "r"(a[3]), "r"(b0), "r"(b1));
}

// swizzled smem offset within a 128x32 bf16 tile: rows of 64B = 4 x 16B chunks,
// chunk ^= (row>>1)&3  -> conflict-free for both cp.async stores and ldmatrix.
__device__ __forceinline__ uint32_t swz(uint32_t tilebase, int row, int ch) {
    return tilebase + (uint32_t)row * 64u + (uint32_t)((ch ^ ((row >> 1) & 3)) << 4);
}

// ---------------- split-bf16 GEMM via mma.sync ----------------
// C[M,N] = (Ah+Al)[M,K] * (Bh+Bl)[N,K]^T (+ Res), fp32 accum.
// grid = (M/128, N/128), 256 threads. Warp tile 64x32 (warps 2x4 over M,N).
template<bool RES>
__global__ void __launch_bounds__(256) gemm_mma(
        const __nv_bfloat16* __restrict__ Ah, const __nv_bfloat16* __restrict__ Al,
        const __nv_bfloat16* __restrict__ Bh, const __nv_bfloat16* __restrict__ Bl,
        const float* __restrict__ Res, float* __restrict__ C,
        int N, int K) {
    extern __shared__ char smem[];
    const uint32_t sb = smem_u32(smem);
    const int tid = threadIdx.x;
    const int lane = tid & 31;
    const int wid = tid >> 5;
    const int warp_m = wid & 1;      // 2 warps over M
    const int warp_n = wid >> 1;     // 4 warps over N
    const int bm = blockIdx.x * BM;
    const int bn = blockIdx.y * BN;
    const int nst = K / KC;
    const size_t rowb = (size_t)K * 2;   // bytes per K-major row

    const char* baseA[2] = { (const char*)Ah + (size_t)bm * rowb,
                             (const char*)Al + (size_t)bm * rowb };
    const char* baseB[2] = { (const char*)Bh + (size_t)bn * rowb,
                             (const char*)Bl + (size_t)bn * rowb };

    // ldmatrix lane decomposition
    const int mat = lane >> 3;          // which 8x8 matrix this lane addresses
    const int i8  = lane & 7;           // row within matrix
    const int mrow_off = ((mat & 1) << 3) + i8;   // 0..15
    const int ch_off = mat >> 1;                  // 0 or 1 (k chunk within k16)

    float acc[4][4][4];
#pragma unroll
    for (int a = 0; a < 4; ++a)
#pragma unroll
        for (int b = 0; b < 4; ++b)
#pragma unroll
            for (int c = 0; c < 4; ++c) acc[a][b][c] = 0.f;

    auto load_stage = [&](int j) {
        const uint32_t stb = sb + (uint32_t)(j & (NSTAGE - 1)) * STAGE_BYTES;
        const size_t koff = (size_t)j * 64;  // KC*2 bytes
#pragma unroll
        for (int tile = 0; tile < 4; ++tile) {
            const char* gb = (tile < 2 ? baseA[tile] : baseB[tile - 2]) + koff;
            const uint32_t tb = stb + (uint32_t)tile * TILEB;
#pragma unroll
            for (int p = 0; p < 2; ++p) {
                int linear = tid + p * 256;
                int row = linear >> 2, ch = linear & 3;
                cpa16(swz(tb, row, ch), gb + (size_t)row * rowb + ch * 16);
            }
        }
        asm volatile("cp.async.commit_group;" ::: "memory");
    };

    for (int j = 0; j < 3; ++j) load_stage(j);

    for (int i = 0; i < nst; ++i) {
        int allow = nst - 1 - i; if (allow > 2) allow = 2;
        if (allow == 2)      asm volatile("cp.async.wait_group 2;" ::: "memory");
        else if (allow == 1) asm volatile("cp.async.wait_group 1;" ::: "memory");
        else                 asm volatile("cp.async.wait_group 0;" ::: "memory");
        __syncthreads();
        if (i + 3 < nst) load_stage(i + 3);

        const uint32_t stb = sb + (uint32_t)(i & (NSTAGE - 1)) * STAGE_BYTES;
#pragma unroll
        for (int h = 0; h < 2; ++h) {
            uint32_t af[2][4][4];
            uint32_t bf[2][2][4];
#pragma unroll
            for (int rep = 0; rep < 2; ++rep) {
                uint32_t tb = stb + (uint32_t)rep * TILEB;
#pragma unroll
                for (int mt = 0; mt < 4; ++mt) {
                    int r = warp_m * 64 + mt * 16 + mrow_off;
                    ldsm4(af[rep][mt], swz(tb, r, h * 2 + ch_off));
                }
            }
#pragma unroll
            for (int rep = 0; rep < 2; ++rep) {
                uint32_t tb = stb + (uint32_t)(2 + rep) * TILEB;
#pragma unroll
                for (int np = 0; np < 2; ++np) {
                    int r = warp_n * 32 + np * 16 + mrow_off;
                    ldsm4(bf[rep][np], swz(tb, r, h * 2 + ch_off));
                }
            }
#pragma unroll
            for (int mt = 0; mt < 4; ++mt)
#pragma unroll
                for (int nt = 0; nt < 4; ++nt) {
                    int np = nt >> 1, sub = nt & 1;
                    float* d = acc[mt][nt];
                    mma16816(d, af[0][mt], bf[0][np][sub], bf[0][np][sub + 2]);  // Ah*Bh
                    mma16816(d, af[0][mt], bf[1][np][sub], bf[1][np][sub + 2]);  // Ah*Bl
                    mma16816(d, af[1][mt], bf[0][np][sub], bf[0][np][sub + 2]);  // Al*Bh
                }
        }
    }

    // epilogue
#pragma unroll
    for (int mt = 0; mt < 4; ++mt)
#pragma unroll
        for (int nt = 0; nt < 4; ++nt) {
            int row = bm + warp_m * 64 + mt * 16 + (lane >> 2);
            int col = bn + warp_n * 32 + nt * 8 + ((lane & 3) << 1);
            float* d = acc[mt][nt];
            size_t o0 = (size_t)row * N + col;
            size_t o1 = (size_t)(row + 8) * N + col;
            if (RES) {
                d[0] += Res[o0]; d[1] += Res[o0 + 1];
                d[2] += Res[o1]; d[3] += Res[o1 + 1];
            }
            *(float2*)(C + o0) = make_float2(d[0], d[1]);
            *(float2*)(C + o1) = make_float2(d[2], d[3]);
        }
}

// ---------------- dequant: one warp per group of 32 along K -> bf16 hi/lo ----------------
__global__ void dequant_kernel(const float* __restrict__ w, __nv_bfloat16* __restrict__ oh,
                               __nv_bfloat16* __restrict__ ol, int ngroups) {
    int gid  = (blockIdx.x * blockDim.x + threadIdx.x) >> 5;
    int lane = threadIdx.x & 31;
    if (gid >= ngroups) return;
    size_t idx = (size_t)gid * 32 + lane;
    float v = w[idx];
    float a = fabsf(v);
#pragma unroll
    for (int off = 16; off; off >>= 1) a = fmaxf(a, __shfl_xor_sync(0xffffffffu, a, off));
    float s = a / 7.0f + 1e-12f;
    float q = fminf(fmaxf(rintf(v / s), -8.0f), 7.0f);
    float val = q * s;
    __nv_bfloat16 h = __float2bfloat16(val);
    oh[idx] = h;
    ol[idx] = __float2bfloat16(val - __bfloat162float(h));
}

// ---------------- embedding gather ----------------
__global__ void embed_kernel(const int* __restrict__ ids, const float* __restrict__ ew,
                             float* __restrict__ h) {
    int s = blockIdx.x;
    int tok = ids[s];
    const float4* src = (const float4*)(ew + (size_t)tok * HID);
    float4* dst = (float4*)(h + (size_t)s * HID);
    for (int i = threadIdx.x; i < HID / 4; i += blockDim.x) dst[i] = src[i];
}

// ---------------- rmsnorm -> bf16 hi/lo ----------------
__global__ void rmsnorm_bf16(const float* __restrict__ x, const float* __restrict__ w,
                             __nv_bfloat16* __restrict__ oh, __nv_bfloat16* __restrict__ ol) {
    int row = blockIdx.x;
    const float* xr = x + (size_t)row * HID;
    float s = 0.f;
    for (int i = threadIdx.x; i < HID; i += 256) { float v = xr[i]; s += v * v; }
#pragma unroll
    for (int off = 16; off; off >>= 1) s += __shfl_xor_sync(0xffffffffu, s, off);
    __shared__ float red[8];
    __shared__ float rtot;
    if ((threadIdx.x & 31) == 0) red[threadIdx.x >> 5] = s;
    __syncthreads();
    if (threadIdx.x == 0) {
        float t = 0.f;
#pragma unroll
        for (int i = 0; i < 8; ++i) t += red[i];
        rtot = rsqrtf(t / (float)HID + EPS_RMS);
    }
    __syncthreads();
    float r = rtot;
    size_t base = (size_t)row * HID;
    for (int i = threadIdx.x; i < HID; i += 256) {
        float v = xr[i] * r * w[i];
        __nv_bfloat16 h = __float2bfloat16(v);
        oh[base + i] = h;
        ol[base + i] = __float2bfloat16(v - __bfloat162float(h));
    }
}

// ---------------- rope (llama half-split), in-place on fused qkv ----------------
__global__ void rope_kernel(float* __restrict__ qkv, const int* __restrict__ pos_ptr) {
    int s = blockIdx.x, h = blockIdx.y, d = threadIdx.x;  // d in [0,64)
    int pos = pos_ptr[0] + s;
    float invf = (float)exp(-((double)(2 * d) / 128.0) * log(10000.0));
    float ang  = (float)pos * invf;
    float cs = (float)cos((double)ang);
    float sn = (float)sin((double)ang);
    size_t base = (size_t)s * QKV_N + h * HD;
    float x1 = qkv[base + d], x2 = qkv[base + d + 64];
    qkv[base + d]      = x1 * cs - x2 * sn;
    qkv[base + d + 64] = x2 * cs + x1 * sn;
    size_t kb = base + HID;
    x1 = qkv[kb + d]; x2 = qkv[kb + d + 64];
    qkv[kb + d]      = x1 * cs - x2 * sn;
    qkv[kb + d + 64] = x2 * cs + x1 * sn;
}

// ---------------- flash attention, fp32, 64q x 32k tiles; out -> bf16 hi/lo ----------------
__global__ void __launch_bounds__(256) attn_kernel(const float* __restrict__ qkv,
                                                   __nv_bfloat16* __restrict__ cth,
                                                   __nv_bfloat16* __restrict__ ctl,
                                                   const int* __restrict__ pos_ptr) {
    __shared__ float Ks[32 * 129];
    __shared__ float Vs[32 * 129];
    __shared__ float Ps[64 * 33];
    const int h = blockIdx.x;
    const int qt = blockIdx.y;
    const int tid = threadIdx.x;
    const int r = tid >> 2;
    const int c = tid & 3;
    const int pid = pos_ptr[0];
    const int s = qt * 64 + r;
    const int pos = pid + s;

    float qreg[32], o[32];
    const float* qp = qkv + (size_t)s * QKV_N + h * HD + c * 32;
#pragma unroll
    for (int i = 0; i < 32; ++i) { qreg[i] = qp[(i + 8 * c) & 31]; o[i] = 0.f; }
    float m = -1e30f, l = 0.f;

    int maxpos = pid + qt * 64 + 63;
    int ntiles = maxpos / 32 + 1;
    if (ntiles > S_LEN / 32) ntiles = S_LEN / 32;

    for (int jt = 0; jt < ntiles; ++jt) {
        __syncthreads();
        for (int idx = tid; idx < 32 * 128; idx += 256) {
            int row = idx >> 7, col = idx & 127;
            size_t g = (size_t)(jt * 32 + row) * QKV_N + h * HD + col;
            Ks[row * 129 + col] = qkv[g + HID];
            Vs[row * 129 + col] = qkv[g + 2 * HID];
        }
        __syncthreads();

        float tmax = -1e30f;
        for (int j = 0; j < 32; ++j) {
            const float* kr = &Ks[j * 129 + c * 32];
            float p = 0.f;
#pragma unroll
            for (int i = 0; i < 32; ++i) p += qreg[i] * kr[(i + 8 * c) & 31];
            p += __shfl_xor_sync(0xffffffffu, p, 1);
            p += __shfl_xor_sync(0xffffffffu, p, 2);
            float val = ((jt * 32 + j) <= pos) ? p * ATT_SCALE : -1e30f;
            tmax = fmaxf(tmax, val);
            if ((j & 3) == c) Ps[r * 33 + j] = val;
        }
        __syncwarp();
        float mnew = fmaxf(m, tmax);
        float sf = expf(m - mnew);
        float tsum = 0.f;
#pragma unroll
        for (int jj = 0; jj < 8; ++jj) {
            int j = jj * 4 + c;
            float e = expf(Ps[r * 33 + j] - mnew);
            Ps[r * 33 + j] = e;
            tsum += e;
        }
        tsum += __shfl_xor_sync(0xffffffffu, tsum, 1);
        tsum += __shfl_xor_sync(0xffffffffu, tsum, 2);
        __syncwarp();
        l = l * sf + tsum;
        m = mnew;
#pragma unroll
        for (int i = 0; i < 32; ++i) o[i] *= sf;
        for (int j = 0; j < 32; ++j) {
            float pv = Ps[r * 33 + j];
            const float* vr = &Vs[j * 129 + c * 32];
#pragma unroll
            for (int i = 0; i < 32; ++i) o[i] += pv * vr[(i + 8 * c) & 31];
        }
    }
    float inv = 1.f / l;
    size_t cbase = (size_t)s * HID + h * HD + c * 32;
#pragma unroll
    for (int i = 0; i < 32; ++i) {
        float v = o[i] * inv;
        __nv_bfloat16 hh = __float2bfloat16(v);
        cth[cbase + ((i + 8 * c) & 31)] = hh;
        ctl[cbase + ((i + 8 * c) & 31)] = __float2bfloat16(v - __bfloat162float(hh));
    }
}

// ---------------- SwiGLU: u = up * gate * sigmoid(gate) -> bf16 hi/lo ----------------
__global__ void silu_mul_kernel(const float* __restrict__ gu, __nv_bfloat16* __restrict__ uh,
                                __nv_bfloat16* __restrict__ ul) {
    int s = blockIdx.x;
    const float* row = gu + (size_t)s * GU_N;
    size_t ob = (size_t)s * INTER;
    for (int j = threadIdx.x; j < INTER; j += 256) {
        float g = row[j];
        float u = row[INTER + j];
        float v = u * g / (1.f + expf(-g));
        __nv_bfloat16 h = __float2bfloat16(v);
        uh[ob + j] = h;
        ul[ob + j] = __float2bfloat16(v - __bfloat162float(h));
    }
}

// ---------------- host orchestration ----------------
static void dequant(const float* w, __nv_bfloat16* dh, __nv_bfloat16* dl, size_t nelem) {
    int ngroups = (int)(nelem / 32);
    int blocks = (int)((nelem + 255) / 256);
    dequant_kernel<<<blocks, 256>>>(w, dh, dl, ngroups);
}

extern "C" void kernel_launch(void* const* d_in, const int* in_sizes, int n_in,
                              void* d_out, int out_size) {
    const int*   input_ids = (const int*)d_in[0];
    const int*   pos_id    = (const int*)d_in[3];
    const float* embed_w   = (const float*)d_in[4];
    const float* in_ln_w   = (const float*)d_in[5];
    const float* post_ln_w = (const float*)d_in[6];
    const float* final_ln  = (const float*)d_in[7];
    const float* q_w       = (const float*)d_in[8];
    const float* k_w       = (const float*)d_in[9];
    const float* v_w       = (const float*)d_in[10];
    const float* o_w       = (const float*)d_in[11];
    const float* gate_w    = (const float*)d_in[12];
    const float* up_w      = (const float*)d_in[13];
    const float* down_w    = (const float*)d_in[14];
    const float* lm_head_w = (const float*)d_in[15];
    float* out = (float*)d_out;

    __nv_bfloat16 *p_wh, *p_wl, *p_xh, *p_xl;
    float *p_h, *p_a, *p_qkv, *p_gu;
    cudaGetSymbolAddress((void**)&p_wh, g_wh);
    cudaGetSymbolAddress((void**)&p_wl, g_wl);
    cudaGetSymbolAddress((void**)&p_xh, g_xh);
    cudaGetSymbolAddress((void**)&p_xl, g_xl);
    cudaGetSymbolAddress((void**)&p_h, g_h);
    cudaGetSymbolAddress((void**)&p_a, g_a);
    cudaGetSymbolAddress((void**)&p_qkv, g_qkv);
    cudaGetSymbolAddress((void**)&p_gu, g_gu);

    cudaFuncSetAttribute(gemm_mma<false>, cudaFuncAttributeMaxDynamicSharedMemorySize, GEMM_SMEM);
    cudaFuncSetAttribute(gemm_mma<true>,  cudaFuncAttributeMaxDynamicSharedMemorySize, GEMM_SMEM);

    const size_t wsq = (size_t)HID * HID;
    const size_t wsg = (size_t)INTER * HID;

    embed_kernel<<<S_LEN, 256>>>(input_ids, embed_w, p_h);

    for (int l = 0; l < L_LAYERS; ++l) {
        rmsnorm_bf16<<<S_LEN, 256>>>(p_h, in_ln_w + l * HID, p_xh, p_xl);

        // fused QKV: dequant q|k|v contiguously, one N=6144 GEMM
        dequant(q_w + l * wsq, p_wh,           p_wl,           wsq);
        dequant(k_w + l * wsq, p_wh + wsq,     p_wl + wsq,     wsq);
        dequant(v_w + l * wsq, p_wh + 2 * wsq, p_wl + 2 * wsq, wsq);
        gemm_mma<false><<<dim3(S_LEN / BM, QKV_N / BN), 256, GEMM_SMEM>>>(
            p_xh, p_xl, p_wh, p_wl, nullptr, p_qkv, QKV_N, HID);

        rope_kernel<<<dim3(S_LEN, NH), 64>>>(p_qkv, pos_id);
        attn_kernel<<<dim3(NH, S_LEN / 64), 256>>>(p_qkv, p_xh, p_xl, pos_id);

        // O-proj + residual
        dequant(o_w + l * wsq, p_wh, p_wl, wsq);
        gemm_mma<true><<<dim3(S_LEN / BM, HID / BN), 256, GEMM_SMEM>>>(
            p_xh, p_xl, p_wh, p_wl, p_h, p_a, HID, HID);

        rmsnorm_bf16<<<S_LEN, 256>>>(p_a, post_ln_w + l * HID, p_xh, p_xl);

        // fused gate|up: one N=11264 GEMM
        dequant(gate_w + l * wsg, p_wh,       p_wl,       wsg);
        dequant(up_w   + l * wsg, p_wh + wsg, p_wl + wsg, wsg);
        gemm_mma<false><<<dim3(S_LEN / BM, GU_N / BN), 256, GEMM_SMEM>>>(
            p_xh, p_xl, p_wh, p_wl, nullptr, p_gu, GU_N, HID);

        silu_mul_kernel<<<S_LEN, 256>>>(p_gu, p_xh, p_xl);

        // down-proj + residual
        dequant(down_w + l * wsg, p_wh, p_wl, wsg);
        gemm_mma<true><<<dim3(S_LEN / BM, HID / BN), 256, GEMM_SMEM>>>(
            p_xh, p_xl, p_wh, p_wl, p_a, p_h, HID, INTER);
    }

    rmsnorm_bf16<<<S_LEN, 256>>>(p_h, final_ln, p_xh, p_xl);
    dequant(lm_head_w, p_wh, p_wl, (size_t)VOCAB * HID);
    gemm_mma<false><<<dim3(S_LEN / BM, VOCAB / BN), 256, GEMM_SMEM>>>(
        p_xh, p_xl, p_wh, p_wl, nullptr, out, VOCAB, HID);
}